// round 13
// baseline (speedup 1.0000x reference)
#include <cuda_runtime.h>
#include <cuda_bf16.h>

typedef unsigned long long u64;
typedef unsigned int u32;

#define B_ 2048
#define I_ 512
#define O_ 256
#define NSEG 7
#define KBIG (NSEG * I_)     // 3584
#define CM 64                // CTA M tile
#define CN 64                // CTA N tile
#define CK 64                // K chunk
#define NCHUNK (KBIG / CK)   // 56
#define NBUF 3
#define GEMM_SMEM (NBUF * 16384)   // per buf: A 8KB + B 8KB

__device__ __align__(256) __nv_bfloat16 Abig[B_ * KBIG];        // 14.7MB
__device__ __align__(256) __nv_bfloat16 Bbig[NSEG * O_ * I_];   // 1.84MB, [seg][n][k]

__device__ __forceinline__ void cpa16(u32 saddr, const void* g) {
    asm volatile("cp.async.cg.shared.global [%0], [%1], 16;" :: "r"(saddr), "l"(g));
}
__device__ __forceinline__ u32 pack2(float lo, float hi) {
    __nv_bfloat162 p = __floats2bfloat162_rn(lo, hi);
    return *(u32*)&p;
}

// ---------------- K1: prep Abig + Bbig ----------------
__global__ __launch_bounds__(256) void l0_prep(
    const float* __restrict__ x, const float* __restrict__ w,
    const float* __restrict__ qz)
{
    const int tid = threadIdx.x;
    if (blockIdx.x < 256) {
        // A part: 8 rows per block; thread handles i-pair 2*tid.
        __shared__ float zs[I_];
        for (int i = tid; i < I_; i += 256) {
            float q = qz[i];
            float pi = 1.0f / (1.0f + expf(-q));
            zs[i] = fminf(fmaxf(fmaf(pi, 1.2f, -0.1f), 0.0f), 1.0f);
        }
        __syncthreads();
        const int i2 = 2 * tid;
        const float z0 = zs[i2], z1 = zs[i2 + 1];
#pragma unroll 1
        for (int r = 0; r < 8; ++r) {
            const int row = blockIdx.x * 8 + r;
            float2 xv = *(const float2*)(x + row * I_ + i2);
            float a0 = fmaf(-xv.x, z0, 1.0f);
            float a1 = fmaf(-xv.y, z1, 1.0f);
            __nv_bfloat16 h0 = __float2bfloat16_rn(a0);
            __nv_bfloat16 h1 = __float2bfloat16_rn(a1);
            float l0 = a0 - __bfloat162float(h0);
            float l1 = a1 - __bfloat162float(h1);
            float s0 = a0 * a0, s1 = a1 * a1;
            u32* dst = (u32*)(Abig + (size_t)row * KBIG + i2);
            __nv_bfloat162 hh; hh.x = h0; hh.y = h1;
            u32 ah2 = *(u32*)&hh;
            dst[0 * (I_ / 2) * 0 + 0] = ah2;            // seg0 at +0
            *(u32*)((__nv_bfloat16*)0 == 0 ? 0 : 0);    // (no-op guard removed below)
            // segment stores (each +512 elements = +256 u32)
            ((u32*)(Abig + (size_t)row * KBIG + 0 * I_ + i2))[0] = ah2;
            ((u32*)(Abig + (size_t)row * KBIG + 1 * I_ + i2))[0] = ah2;
            ((u32*)(Abig + (size_t)row * KBIG + 2 * I_ + i2))[0] = pack2(l0, l1);
            ((u32*)(Abig + (size_t)row * KBIG + 3 * I_ + i2))[0] = pack2(s0, s1);
            ((u32*)(Abig + (size_t)row * KBIG + 4 * I_ + i2))[0] = pack2(s0 * a0, s1 * a1);
            ((u32*)(Abig + (size_t)row * KBIG + 5 * I_ + i2))[0] = pack2(s0 * s0, s1 * s1);
            ((u32*)(Abig + (size_t)row * KBIG + 6 * I_ + i2))[0] = pack2(s0 * s0 * a0, s1 * s1 * a1);
        }
    } else {
        // B part: 32 blocks; tile (kt,nt) of 64x64; write transposed [seg][n][k].
        __shared__ float wbuf[64][65];
        const int bt = blockIdx.x - 256;
        const int k0 = (bt >> 2) * 64;
        const int n0 = (bt & 3) * 64;
#pragma unroll
        for (int j = 0; j < 16; ++j) {
            int idx = tid + 256 * j;
            int kr = idx >> 6, nc = idx & 63;
            wbuf[kr][nc] = w[(k0 + kr) * O_ + n0 + nc];
        }
        __syncthreads();
        const int nf = tid >> 2;            // 0..63
        const int ks = (tid & 3) * 16;      // 16 k's per thread
#pragma unroll
        for (int j = 0; j < 8; ++j) {
            int kk = ks + 2 * j;
            float w0 = wbuf[kk][nf], w1 = wbuf[kk + 1][nf];
            __nv_bfloat16 h0 = __float2bfloat16_rn(w0);
            __nv_bfloat16 h1 = __float2bfloat16_rn(w1);
            float l0 = w0 - __bfloat162float(h0);
            float l1 = w1 - __bfloat162float(h1);
            float s0 = w0 * w0, s1 = w1 * w1;
            __nv_bfloat162 hh; hh.x = h0; hh.y = h1;
            u32 wh2 = *(u32*)&hh;
            size_t base = (size_t)(n0 + nf) * I_ + k0 + kk;
            size_t segstr = (size_t)O_ * I_;
            *(u32*)(Bbig + base + 0 * segstr) = wh2;
            *(u32*)(Bbig + base + 1 * segstr) = pack2(l0, l1);
            *(u32*)(Bbig + base + 2 * segstr) = wh2;
            *(u32*)(Bbig + base + 3 * segstr) = pack2(s0 * 0.5f, s1 * 0.5f);
            *(u32*)(Bbig + base + 4 * segstr) = pack2(s0 * w0 * (1.f/3.f), s1 * w1 * (1.f/3.f));
            *(u32*)(Bbig + base + 5 * segstr) = pack2(s0 * s0 * 0.25f, s1 * s1 * 0.25f);
            *(u32*)(Bbig + base + 6 * segstr) = pack2(s0 * s0 * w0 * 0.2f, s1 * s1 * w1 * 0.2f);
        }
    }
}

// ---------------- K2: GEMM (bf16 HMMA) + fused exp epilogue ----------------
__global__ __launch_bounds__(256) void l0_gemm(float* __restrict__ out)
{
    extern __shared__ __align__(1024) char smem[];
    const u32 sb = (u32)__cvta_generic_to_shared(smem);

    const int tid = threadIdx.x;
    const int lane = tid & 31;
    const int wid = tid >> 5;
    const int mW = (wid >> 2) * 32;   // warp M offset in CTA tile
    const int nW = (wid & 3) * 16;    // warp N offset
    const int m0 = (blockIdx.x >> 2) * CM;
    const int n0 = (blockIdx.x & 3) * CN;

    // Per-chunk copy: 512 A units + 512 B units of 16B; thread does 2+2.
#define PREF(c, buf)                                                             \
    {                                                                            \
        if ((c) < NCHUNK) {                                                      \
            const int seg = (c) >> 3;                                            \
            const int ii0 = ((c) & 7) * CK;                                      \
            _Pragma("unroll") for (int h = 0; h < 2; ++h) {                      \
                int u = tid + h * 256;                                           \
                int r = u >> 3, c8 = u & 7;                                      \
                u32 off = (u32)(r * 128 + (c8 * 16 ^ ((r & 7) * 16)));           \
                cpa16(sb + (buf) * 16384 + off,                                  \
                      Abig + (size_t)(m0 + r) * KBIG + (c) * CK + c8 * 8);       \
                cpa16(sb + (buf) * 16384 + 8192 + off,                           \
                      Bbig + ((size_t)seg * O_ + n0 + r) * I_ + ii0 + c8 * 8);   \
            }                                                                    \
        }                                                                        \
        asm volatile("cp.async.commit_group;");                                  \
    }

    PREF(0, 0);
    PREF(1, 1);

    float acc[2][2][4];
#pragma unroll
    for (int mt = 0; mt < 2; ++mt)
#pragma unroll
        for (int nt = 0; nt < 2; ++nt)
#pragma unroll
            for (int e = 0; e < 4; ++e) acc[mt][nt][e] = 0.0f;

    const int rowAin = lane & 15;
    const int kcA = (lane >> 4) * 16;
    const int rowBin = lane & 7;
    const int kcB = ((lane >> 3) & 1) * 16;
    const u32 swzA = (u32)((lane & 7) * 16);

#pragma unroll 1
    for (int c = 0; c < NCHUNK; ++c) {
        // Proven protocol: wait (group c landed for THIS thread) + barrier
        // (all threads' copies of chunk c visible; all done computing c-1,
        //  so buffer (c+2)%3 == (c-1)%3 is free to overwrite).
        asm volatile("cp.async.wait_group 1;");
        __syncthreads();
        PREF(c + 2, (c + 2) % NBUF);

        const u32 sA = sb + (c % NBUF) * 16384;
        const u32 sB = sA + 8192;
#pragma unroll
        for (int ks = 0; ks < 4; ++ks) {
            u32 aF[2][4], bF[2][2];
#pragma unroll
            for (int mt = 0; mt < 2; ++mt) {
                u32 byte = (u32)((mW + mt * 16 + rowAin) * 128 + ks * 32 + kcA) ^ swzA;
                asm volatile("ldmatrix.sync.aligned.m8n8.x4.shared.b16 {%0,%1,%2,%3}, [%4];"
                             : "=r"(aF[mt][0]), "=r"(aF[mt][1]), "=r"(aF[mt][2]), "=r"(aF[mt][3])
                             : "r"(sA + byte));
            }
#pragma unroll
            for (int nt = 0; nt < 2; ++nt) {
                u32 byte = (u32)((nW + nt * 8 + rowBin) * 128 + ks * 32 + kcB) ^ swzA;
                asm volatile("ldmatrix.sync.aligned.m8n8.x2.shared.b16 {%0,%1}, [%2];"
                             : "=r"(bF[nt][0]), "=r"(bF[nt][1])
                             : "r"(sB + byte));
            }
#pragma unroll
            for (int mt = 0; mt < 2; ++mt)
#pragma unroll
                for (int nt = 0; nt < 2; ++nt)
                    asm volatile(
                        "mma.sync.aligned.m16n8k16.row.col.f32.bf16.bf16.f32 "
                        "{%0,%1,%2,%3}, {%4,%5,%6,%7}, {%8,%9}, {%0,%1,%2,%3};"
                        : "+f"(acc[mt][nt][0]), "+f"(acc[mt][nt][1]),
                          "+f"(acc[mt][nt][2]), "+f"(acc[mt][nt][3])
                        : "r"(aF[mt][0]), "r"(aF[mt][1]), "r"(aF[mt][2]), "r"(aF[mt][3]),
                          "r"(bF[nt][0]), "r"(bF[nt][1]));
        }
    }

    // Epilogue: out = exp(-S). c-frag: c0,c1 -> (row l>>2, col 2(l&3)+{0,1}); c2,c3 -> row+8.
    const int r0 = m0 + mW + (lane >> 2);
    const int cB = n0 + nW + (lane & 3) * 2;
#pragma unroll
    for (int mt = 0; mt < 2; ++mt)
#pragma unroll
        for (int nt = 0; nt < 2; ++nt) {
            int rr = r0 + mt * 16;
            int cc = cB + nt * 8;
            *(float2*)(out + rr * O_ + cc) =
                make_float2(expf(-acc[mt][nt][0]), expf(-acc[mt][nt][1]));
            *(float2*)(out + (rr + 8) * O_ + cc) =
                make_float2(expf(-acc[mt][nt][2]), expf(-acc[mt][nt][3]));
        }
}

extern "C" void kernel_launch(void* const* d_in, const int* in_sizes, int n_in,
                              void* d_out, int out_size) {
    const float* x = nullptr;
    const float* w = nullptr;
    const float* qz = nullptr;
    for (int i = 0; i < n_in; ++i) {
        if (in_sizes[i] == B_ * I_)      x  = (const float*)d_in[i];
        else if (in_sizes[i] == I_ * O_) w  = (const float*)d_in[i];
        else if (in_sizes[i] == I_)      qz = (const float*)d_in[i];
    }
    cudaFuncSetAttribute(l0_gemm, cudaFuncAttributeMaxDynamicSharedMemorySize, GEMM_SMEM);
    l0_prep<<<288, 256>>>(x, w, qz);
    l0_gemm<<<(B_ / CM) * (O_ / CN), 256, GEMM_SMEM>>>((float*)d_out);
}

// round 14
// speedup vs baseline: 1.0963x; 1.0963x over previous
#include <cuda_runtime.h>
#include <cuda_bf16.h>

typedef unsigned long long u64;
typedef unsigned int u32;

#define B_ 2048
#define I_ 512
#define O_ 256
#define NSEG 7
#define KBIG (NSEG * I_)     // 3584
#define CM 32                // CTA M tile
#define CN 64                // CTA N tile
#define CK 64                // K chunk
#define NCHUNK (KBIG / CK)   // 56
#define NBUF 4
#define BUFSZ 12288          // A 4KB + B 8KB
#define GEMM_SMEM (NBUF * BUFSZ)   // 48KB

__device__ __align__(256) __nv_bfloat16 Abig[B_ * KBIG];        // 14.7MB
__device__ __align__(256) __nv_bfloat16 Bbig[NSEG * O_ * I_];   // 1.84MB, [seg][n][k]

__device__ __forceinline__ void cpa16(u32 saddr, const void* g) {
    asm volatile("cp.async.cg.shared.global [%0], [%1], 16;" :: "r"(saddr), "l"(g));
}
__device__ __forceinline__ u32 pack2(float lo, float hi) {
    __nv_bfloat162 p = __floats2bfloat162_rn(lo, hi);
    return *(u32*)&p;
}

// ---------------- K1: prep Abig + Bbig ----------------
__global__ __launch_bounds__(256) void l0_prep(
    const float* __restrict__ x, const float* __restrict__ w,
    const float* __restrict__ qz)
{
    const int tid = threadIdx.x;
    if (blockIdx.x < 256) {
        // A part: 8 rows per block; thread handles i-pair 2*tid.
        __shared__ float zs[I_];
        for (int i = tid; i < I_; i += 256) {
            float q = qz[i];
            float pi = 1.0f / (1.0f + expf(-q));
            zs[i] = fminf(fmaxf(fmaf(pi, 1.2f, -0.1f), 0.0f), 1.0f);
        }
        __syncthreads();
        const int i2 = 2 * tid;
        const float z0 = zs[i2], z1 = zs[i2 + 1];
#pragma unroll 1
        for (int r = 0; r < 8; ++r) {
            const int row = blockIdx.x * 8 + r;
            float2 xv = *(const float2*)(x + row * I_ + i2);
            float a0 = fmaf(-xv.x, z0, 1.0f);
            float a1 = fmaf(-xv.y, z1, 1.0f);
            __nv_bfloat16 h0 = __float2bfloat16_rn(a0);
            __nv_bfloat16 h1 = __float2bfloat16_rn(a1);
            float l0 = a0 - __bfloat162float(h0);
            float l1 = a1 - __bfloat162float(h1);
            float s0 = a0 * a0, s1 = a1 * a1;
            __nv_bfloat162 hh; hh.x = h0; hh.y = h1;
            u32 ah2 = *(u32*)&hh;
            __nv_bfloat16* base = Abig + (size_t)row * KBIG + i2;
            *(u32*)(base + 0 * I_) = ah2;
            *(u32*)(base + 1 * I_) = ah2;
            *(u32*)(base + 2 * I_) = pack2(l0, l1);
            *(u32*)(base + 3 * I_) = pack2(s0, s1);
            *(u32*)(base + 4 * I_) = pack2(s0 * a0, s1 * a1);
            *(u32*)(base + 5 * I_) = pack2(s0 * s0, s1 * s1);
            *(u32*)(base + 6 * I_) = pack2(s0 * s0 * a0, s1 * s1 * a1);
        }
    } else {
        // B part: 32 blocks; tile (kt,nt) of 64x64; write transposed [seg][n][k].
        __shared__ float wbuf[64][65];
        const int bt = blockIdx.x - 256;
        const int k0 = (bt >> 2) * 64;
        const int n0 = (bt & 3) * 64;
#pragma unroll
        for (int j = 0; j < 16; ++j) {
            int idx = tid + 256 * j;
            int kr = idx >> 6, nc = idx & 63;
            wbuf[kr][nc] = w[(k0 + kr) * O_ + n0 + nc];
        }
        __syncthreads();
        const int nf = tid >> 2;            // 0..63
        const int ks = (tid & 3) * 16;      // 16 k's per thread
#pragma unroll
        for (int j = 0; j < 8; ++j) {
            int kk = ks + 2 * j;
            float w0 = wbuf[kk][nf], w1 = wbuf[kk + 1][nf];
            __nv_bfloat16 h0 = __float2bfloat16_rn(w0);
            __nv_bfloat16 h1 = __float2bfloat16_rn(w1);
            float l0 = w0 - __bfloat162float(h0);
            float l1 = w1 - __bfloat162float(h1);
            float s0 = w0 * w0, s1 = w1 * w1;
            __nv_bfloat162 hh; hh.x = h0; hh.y = h1;
            u32 wh2 = *(u32*)&hh;
            size_t base = (size_t)(n0 + nf) * I_ + k0 + kk;
            size_t segstr = (size_t)O_ * I_;
            *(u32*)(Bbig + base + 0 * segstr) = wh2;
            *(u32*)(Bbig + base + 1 * segstr) = pack2(l0, l1);
            *(u32*)(Bbig + base + 2 * segstr) = wh2;
            *(u32*)(Bbig + base + 3 * segstr) = pack2(s0 * 0.5f, s1 * 0.5f);
            *(u32*)(Bbig + base + 4 * segstr) = pack2(s0 * w0 * (1.f/3.f), s1 * w1 * (1.f/3.f));
            *(u32*)(Bbig + base + 5 * segstr) = pack2(s0 * s0 * 0.25f, s1 * s1 * 0.25f);
            *(u32*)(Bbig + base + 6 * segstr) = pack2(s0 * s0 * w0 * 0.2f, s1 * s1 * w1 * 0.2f);
        }
    }
}

// ---------------- K2: GEMM (bf16 HMMA) + fused exp epilogue ----------------
__global__ __launch_bounds__(256) void l0_gemm(float* __restrict__ out)
{
    extern __shared__ __align__(1024) char smem[];
    const u32 sb = (u32)__cvta_generic_to_shared(smem);

    const int tid = threadIdx.x;
    const int lane = tid & 31;
    const int wid = tid >> 5;
    const int mW = (wid >> 2) * 16;   // warp M offset in CTA tile (0,16)
    const int nW = (wid & 3) * 16;    // warp N offset (0..48)
    const int m0 = (blockIdx.x >> 2) * CM;
    const int n0 = (blockIdx.x & 3) * CN;

    // Per-chunk copy: A 256 x 16B units (1/thread) + B 512 units (2/thread).
#define PREF(c, buf)                                                             \
    {                                                                            \
        if ((c) < NCHUNK) {                                                      \
            const int seg = (c) >> 3;                                            \
            const int ii0 = ((c) & 7) * CK;                                      \
            {                                                                    \
                int r = tid >> 3, c8 = tid & 7;                                  \
                u32 off = (u32)(r * 128 + (c8 * 16 ^ ((r & 7) * 16)));           \
                cpa16(sb + (buf) * BUFSZ + off,                                  \
                      Abig + (size_t)(m0 + r) * KBIG + (c) * CK + c8 * 8);       \
            }                                                                    \
            _Pragma("unroll") for (int h = 0; h < 2; ++h) {                      \
                int u = tid + h * 256;                                           \
                int r = u >> 3, c8 = u & 7;                                      \
                u32 off = (u32)(r * 128 + (c8 * 16 ^ ((r & 7) * 16)));           \
                cpa16(sb + (buf) * BUFSZ + 4096 + off,                           \
                      Bbig + ((size_t)seg * O_ + n0 + r) * I_ + ii0 + c8 * 8);   \
            }                                                                    \
        }                                                                        \
        asm volatile("cp.async.commit_group;");                                  \
    }

    PREF(0, 0);
    PREF(1, 1);
    PREF(2, 2);

    float acc[2][4];
#pragma unroll
    for (int nt = 0; nt < 2; ++nt)
#pragma unroll
        for (int e = 0; e < 4; ++e) acc[nt][e] = 0.0f;

    const int rowAin = lane & 15;
    const int kcA = (lane >> 4) * 16;
    const int rowBin = lane & 7;
    const int kcB = ((lane >> 3) & 1) * 16;
    const u32 swzA = (u32)((lane & 7) * 16);

#pragma unroll 1
    for (int c = 0; c < NCHUNK; ++c) {
        // Proven protocol: wait_group 2 -> this thread's commits through chunk c
        // landed; __syncthreads -> all threads' copies of chunk c visible, and
        // all finished computing c-1, so slot (c+3)&3 (last held c-1) is free.
        asm volatile("cp.async.wait_group 2;");
        __syncthreads();
        PREF(c + 3, (c + 3) & (NBUF - 1));

        const u32 sA = sb + (c & (NBUF - 1)) * BUFSZ;
        const u32 sB = sA + 4096;
#pragma unroll
        for (int ks = 0; ks < 4; ++ks) {
            u32 aF[4], bF[2][2];
            {
                u32 byte = (u32)((mW + rowAin) * 128 + ks * 32 + kcA) ^ swzA;
                asm volatile("ldmatrix.sync.aligned.m8n8.x4.shared.b16 {%0,%1,%2,%3}, [%4];"
                             : "=r"(aF[0]), "=r"(aF[1]), "=r"(aF[2]), "=r"(aF[3])
                             : "r"(sA + byte));
            }
#pragma unroll
            for (int nt = 0; nt < 2; ++nt) {
                u32 byte = (u32)((nW + nt * 8 + rowBin) * 128 + ks * 32 + kcB) ^ swzA;
                asm volatile("ldmatrix.sync.aligned.m8n8.x2.shared.b16 {%0,%1}, [%2];"
                             : "=r"(bF[nt][0]), "=r"(bF[nt][1])
                             : "r"(sB + byte));
            }
#pragma unroll
            for (int nt = 0; nt < 2; ++nt)
                asm volatile(
                    "mma.sync.aligned.m16n8k16.row.col.f32.bf16.bf16.f32 "
                    "{%0,%1,%2,%3}, {%4,%5,%6,%7}, {%8,%9}, {%0,%1,%2,%3};"
                    : "+f"(acc[nt][0]), "+f"(acc[nt][1]),
                      "+f"(acc[nt][2]), "+f"(acc[nt][3])
                    : "r"(aF[0]), "r"(aF[1]), "r"(aF[2]), "r"(aF[3]),
                      "r"(bF[nt][0]), "r"(bF[nt][1]));
        }
    }

    // Epilogue: out = exp(-S). c0,c1 -> (row lane>>2, col 2(lane&3)+{0,1}); c2,c3 -> row+8.
    const int r0 = m0 + mW + (lane >> 2);
    const int cB = n0 + nW + (lane & 3) * 2;
#pragma unroll
    for (int nt = 0; nt < 2; ++nt) {
        int cc = cB + nt * 8;
        *(float2*)(out + r0 * O_ + cc) =
            make_float2(expf(-acc[nt][0]), expf(-acc[nt][1]));
        *(float2*)(out + (r0 + 8) * O_ + cc) =
            make_float2(expf(-acc[nt][2]), expf(-acc[nt][3]));
    }
}

extern "C" void kernel_launch(void* const* d_in, const int* in_sizes, int n_in,
                              void* d_out, int out_size) {
    const float* x = nullptr;
    const float* w = nullptr;
    const float* qz = nullptr;
    for (int i = 0; i < n_in; ++i) {
        if (in_sizes[i] == B_ * I_)      x  = (const float*)d_in[i];
        else if (in_sizes[i] == I_ * O_) w  = (const float*)d_in[i];
        else if (in_sizes[i] == I_)      qz = (const float*)d_in[i];
    }
    cudaFuncSetAttribute(l0_gemm, cudaFuncAttributeMaxDynamicSharedMemorySize, GEMM_SMEM);
    l0_prep<<<288, 256>>>(x, w, qz);
    l0_gemm<<<(B_ / CM) * (O_ / CN), 256, GEMM_SMEM>>>((float*)d_out);
}

// round 15
// speedup vs baseline: 1.2361x; 1.1275x over previous
#include <cuda_runtime.h>
#include <cuda_bf16.h>

typedef unsigned long long u64;
typedef unsigned int u32;

#define B_ 2048
#define I_ 512
#define O_ 256
#define NSEG 7
#define KBIG (NSEG * I_)     // 3584
#define CM 32                // CTA M tile
#define CN 64                // CTA N tile
#define CK 64                // K chunk
#define NCHUNK (KBIG / CK)   // 56
#define NBUF 4
#define BUFSZ 12288          // A 4KB + B 8KB
#define GEMM_SMEM (NBUF * BUFSZ)   // 48KB (psum reuses first 32KB post-mainloop)

__device__ __align__(256) __nv_bfloat16 Abig[B_ * KBIG];        // 14.7MB
__device__ __align__(256) __nv_bfloat16 Bbig[NSEG * O_ * I_];   // 1.84MB, [seg][n][k]

__device__ __forceinline__ void cpa16(u32 saddr, const void* g) {
    asm volatile("cp.async.cg.shared.global [%0], [%1], 16;" :: "r"(saddr), "l"(g));
}
__device__ __forceinline__ u32 pack2(float lo, float hi) {
    __nv_bfloat162 p = __floats2bfloat162_rn(lo, hi);
    return *(u32*)&p;
}

// ---------------- K1: prep Abig + Bbig ----------------
__global__ __launch_bounds__(256) void l0_prep(
    const float* __restrict__ x, const float* __restrict__ w,
    const float* __restrict__ qz)
{
    const int tid = threadIdx.x;
    if (blockIdx.x < 256) {
        __shared__ float zs[I_];
        for (int i = tid; i < I_; i += 256) {
            float q = qz[i];
            float pi = 1.0f / (1.0f + expf(-q));
            zs[i] = fminf(fmaxf(fmaf(pi, 1.2f, -0.1f), 0.0f), 1.0f);
        }
        __syncthreads();
        const int i2 = 2 * tid;
        const float z0 = zs[i2], z1 = zs[i2 + 1];
#pragma unroll 1
        for (int r = 0; r < 8; ++r) {
            const int row = blockIdx.x * 8 + r;
            float2 xv = *(const float2*)(x + row * I_ + i2);
            float a0 = fmaf(-xv.x, z0, 1.0f);
            float a1 = fmaf(-xv.y, z1, 1.0f);
            __nv_bfloat16 h0 = __float2bfloat16_rn(a0);
            __nv_bfloat16 h1 = __float2bfloat16_rn(a1);
            float l0 = a0 - __bfloat162float(h0);
            float l1 = a1 - __bfloat162float(h1);
            float s0 = a0 * a0, s1 = a1 * a1;
            __nv_bfloat162 hh; hh.x = h0; hh.y = h1;
            u32 ah2 = *(u32*)&hh;
            __nv_bfloat16* base = Abig + (size_t)row * KBIG + i2;
            *(u32*)(base + 0 * I_) = ah2;
            *(u32*)(base + 1 * I_) = ah2;
            *(u32*)(base + 2 * I_) = pack2(l0, l1);
            *(u32*)(base + 3 * I_) = pack2(s0, s1);
            *(u32*)(base + 4 * I_) = pack2(s0 * a0, s1 * a1);
            *(u32*)(base + 5 * I_) = pack2(s0 * s0, s1 * s1);
            *(u32*)(base + 6 * I_) = pack2(s0 * s0 * a0, s1 * s1 * a1);
        }
    } else {
        __shared__ float wbuf[64][65];
        const int bt = blockIdx.x - 256;
        const int k0 = (bt >> 2) * 64;
        const int n0 = (bt & 3) * 64;
#pragma unroll
        for (int j = 0; j < 16; ++j) {
            int idx = tid + 256 * j;
            int kr = idx >> 6, nc = idx & 63;
            wbuf[kr][nc] = w[(k0 + kr) * O_ + n0 + nc];
        }
        __syncthreads();
        const int nf = tid >> 2;
        const int ks = (tid & 3) * 16;
#pragma unroll
        for (int j = 0; j < 8; ++j) {
            int kk = ks + 2 * j;
            float w0 = wbuf[kk][nf], w1 = wbuf[kk + 1][nf];
            __nv_bfloat16 h0 = __float2bfloat16_rn(w0);
            __nv_bfloat16 h1 = __float2bfloat16_rn(w1);
            float l0 = w0 - __bfloat162float(h0);
            float l1 = w1 - __bfloat162float(h1);
            float s0 = w0 * w0, s1 = w1 * w1;
            __nv_bfloat162 hh; hh.x = h0; hh.y = h1;
            u32 wh2 = *(u32*)&hh;
            size_t base = (size_t)(n0 + nf) * I_ + k0 + kk;
            size_t segstr = (size_t)O_ * I_;
            *(u32*)(Bbig + base + 0 * segstr) = wh2;
            *(u32*)(Bbig + base + 1 * segstr) = pack2(l0, l1);
            *(u32*)(Bbig + base + 2 * segstr) = wh2;
            *(u32*)(Bbig + base + 3 * segstr) = pack2(s0 * 0.5f, s1 * 0.5f);
            *(u32*)(Bbig + base + 4 * segstr) = pack2(s0 * w0 * (1.f/3.f), s1 * w1 * (1.f/3.f));
            *(u32*)(Bbig + base + 5 * segstr) = pack2(s0 * s0 * 0.25f, s1 * s1 * 0.25f);
            *(u32*)(Bbig + base + 6 * segstr) = pack2(s0 * s0 * w0 * 0.2f, s1 * s1 * w1 * 0.2f);
        }
    }
}

// ---------------- K2: GEMM, warp-split-K, 32x32 warp tiles ----------------
__global__ __launch_bounds__(256) void l0_gemm(float* __restrict__ out)
{
    extern __shared__ __align__(1024) char smem[];
    const u32 sb = (u32)__cvta_generic_to_shared(smem);

    const int tid = threadIdx.x;
    const int lane = tid & 31;
    const int wid = tid >> 5;
    const int wn = wid >> 2;          // N-half (0,1) -> n offset 32*wn
    const int wk = wid & 3;           // K-quarter -> k16 slice wk*16 within chunk
    const int m0 = (blockIdx.x >> 2) * CM;
    const int n0 = (blockIdx.x & 3) * CN;

#define PREF(c, buf)                                                             \
    {                                                                            \
        if ((c) < NCHUNK) {                                                      \
            const int seg = (c) >> 3;                                            \
            const int ii0 = ((c) & 7) * CK;                                      \
            {                                                                    \
                int r = tid >> 3, c8 = tid & 7;                                  \
                u32 off = (u32)(r * 128 + (c8 * 16 ^ ((r & 7) * 16)));           \
                cpa16(sb + (buf) * BUFSZ + off,                                  \
                      Abig + (size_t)(m0 + r) * KBIG + (c) * CK + c8 * 8);       \
            }                                                                    \
            _Pragma("unroll") for (int h = 0; h < 2; ++h) {                      \
                int u = tid + h * 256;                                           \
                int r = u >> 3, c8 = u & 7;                                      \
                u32 off = (u32)(r * 128 + (c8 * 16 ^ ((r & 7) * 16)));           \
                cpa16(sb + (buf) * BUFSZ + 4096 + off,                           \
                      Bbig + ((size_t)seg * O_ + n0 + r) * I_ + ii0 + c8 * 8);   \
            }                                                                    \
        }                                                                        \
        asm volatile("cp.async.commit_group;");                                  \
    }

    PREF(0, 0);
    PREF(1, 1);
    PREF(2, 2);

    float acc[2][4][4];   // [mt][nt][frag]
#pragma unroll
    for (int mt = 0; mt < 2; ++mt)
#pragma unroll
        for (int nt = 0; nt < 4; ++nt)
#pragma unroll
            for (int e = 0; e < 4; ++e) acc[mt][nt][e] = 0.0f;

    // ldmatrix address components (k column within chunk is wk*32 bytes + half)
    const int rowAin = lane & 15;                       // A: row within m16 tile
    const u32 colA = (u32)(wk * 32 + (lane >> 4) * 16); // A: k-byte (x4: half sel)
    const int rowBin = lane & 7;                        // B: row within n8 tile
    const u32 colB = (u32)(wk * 32 + ((lane >> 3) & 1) * 16); // B: x2 half sel

#pragma unroll 1
    for (int c = 0; c < NCHUNK; ++c) {
        // Proven protocol: wait_group 2 + barrier => chunk c fully visible,
        // all threads past chunk c-1 => slot (c+3)&3 free to overwrite.
        asm volatile("cp.async.wait_group 2;");
        __syncthreads();
        PREF(c + 3, (c + 3) & (NBUF - 1));

        const u32 sA = sb + (c & (NBUF - 1)) * BUFSZ;
        const u32 sB = sA + 4096;

        u32 aF[2][4], bF[4][2];
#pragma unroll
        for (int mt = 0; mt < 2; ++mt) {
            u32 row = (u32)(mt * 16 + rowAin);
            u32 byte = row * 128 + (colA ^ ((row & 7) * 16));
            asm volatile("ldmatrix.sync.aligned.m8n8.x4.shared.b16 {%0,%1,%2,%3}, [%4];"
                         : "=r"(aF[mt][0]), "=r"(aF[mt][1]), "=r"(aF[mt][2]), "=r"(aF[mt][3])
                         : "r"(sA + byte));
        }
#pragma unroll
        for (int nt = 0; nt < 4; ++nt) {
            u32 row = (u32)(wn * 32 + nt * 8 + rowBin);
            u32 byte = row * 128 + (colB ^ ((row & 7) * 16));
            asm volatile("ldmatrix.sync.aligned.m8n8.x2.shared.b16 {%0,%1}, [%2];"
                         : "=r"(bF[nt][0]), "=r"(bF[nt][1])
                         : "r"(sB + byte));
        }
#pragma unroll
        for (int mt = 0; mt < 2; ++mt)
#pragma unroll
            for (int nt = 0; nt < 4; ++nt)
                asm volatile(
                    "mma.sync.aligned.m16n8k16.row.col.f32.bf16.bf16.f32 "
                    "{%0,%1,%2,%3}, {%4,%5,%6,%7}, {%8,%9}, {%0,%1,%2,%3};"
                    : "+f"(acc[mt][nt][0]), "+f"(acc[mt][nt][1]),
                      "+f"(acc[mt][nt][2]), "+f"(acc[mt][nt][3])
                    : "r"(aF[mt][0]), "r"(aF[mt][1]), "r"(aF[mt][2]), "r"(aF[mt][3]),
                      "r"(bF[nt][0]), "r"(bF[nt][1]));
    }

    // Drain all pending cp.async before repurposing the ring smem as psum.
    asm volatile("cp.async.wait_group 0;");
    __syncthreads();

    // psum[wid][32][32] f32 (32KB, reuses ring). Frag (c0,c1)->(row l>>2, col 2(l&3));
    // (c2,c3)->row+8.
    float* psum = (float*)smem;
    {
        float* pw = psum + wid * (32 * 32);
        const int r0 = lane >> 2;
        const int c0 = (lane & 3) * 2;
#pragma unroll
        for (int mt = 0; mt < 2; ++mt)
#pragma unroll
            for (int nt = 0; nt < 4; ++nt) {
                float* t = pw + (mt * 16 + r0) * 32 + nt * 8 + c0;
                *(float2*)(t)          = make_float2(acc[mt][nt][0], acc[mt][nt][1]);
                *(float2*)(t + 8 * 32) = make_float2(acc[mt][nt][2], acc[mt][nt][3]);
            }
    }
    __syncthreads();

    // Reduce over the 4 K-quarters in fixed order; out = exp(-S).
#pragma unroll
    for (int j = 0; j < 8; ++j) {
        int idx = tid + 256 * j;          // 0..2047 over 32x64 tile
        int m = idx >> 6;
        int n = idx & 63;
        const float* pq = psum + ((n >> 5) * 4) * (32 * 32) + m * 32 + (n & 31);
        float s = pq[0] + pq[1024] + pq[2048] + pq[3072];
        out[(m0 + m) * O_ + n0 + n] = expf(-s);
    }
}

extern "C" void kernel_launch(void* const* d_in, const int* in_sizes, int n_in,
                              void* d_out, int out_size) {
    const float* x = nullptr;
    const float* w = nullptr;
    const float* qz = nullptr;
    for (int i = 0; i < n_in; ++i) {
        if (in_sizes[i] == B_ * I_)      x  = (const float*)d_in[i];
        else if (in_sizes[i] == I_ * O_) w  = (const float*)d_in[i];
        else if (in_sizes[i] == I_)      qz = (const float*)d_in[i];
    }
    cudaFuncSetAttribute(l0_gemm, cudaFuncAttributeMaxDynamicSharedMemorySize, GEMM_SMEM);
    l0_prep<<<288, 256>>>(x, w, qz);
    l0_gemm<<<(B_ / CM) * (O_ / CN), 256, GEMM_SMEM>>>((float*)d_out);
}

// round 16
// speedup vs baseline: 1.3372x; 1.0817x over previous
#include <cuda_runtime.h>
#include <cuda_bf16.h>

typedef unsigned long long u64;
typedef unsigned int u32;

#define B_ 2048
#define I_ 512
#define O_ 256
#define NSEG 7
#define KBIG (NSEG * I_)     // 3584
#define CM 32                // CTA M tile
#define CN 64                // CTA N tile
#define CK 64                // K chunk
#define NCHUNK (KBIG / CK)   // 56
#define NPAIR (NCHUNK / 2)   // 28
#define CBUF 12288           // per chunk: A 4KB + B 8KB
#define PBUF (2 * CBUF)      // pair buffer 24KB
#define GEMM_SMEM (3 * PBUF) // 72KB

__device__ __align__(256) __nv_bfloat16 Abig[B_ * KBIG];        // 14.7MB
__device__ __align__(256) __nv_bfloat16 Bbig[NSEG * O_ * I_];   // 1.84MB, [seg][n][k]

__device__ __forceinline__ void cpa16(u32 saddr, const void* g) {
    asm volatile("cp.async.cg.shared.global [%0], [%1], 16;" :: "r"(saddr), "l"(g));
}
__device__ __forceinline__ u32 pack2(float lo, float hi) {
    __nv_bfloat162 p = __floats2bfloat162_rn(lo, hi);
    return *(u32*)&p;
}

// ---------------- K1: prep Abig + Bbig ----------------
__global__ __launch_bounds__(256) void l0_prep(
    const float* __restrict__ x, const float* __restrict__ w,
    const float* __restrict__ qz)
{
    const int tid = threadIdx.x;
    if (blockIdx.x < 256) {
        __shared__ float zs[I_];
        for (int i = tid; i < I_; i += 256) {
            float q = qz[i];
            float pi = 1.0f / (1.0f + expf(-q));
            zs[i] = fminf(fmaxf(fmaf(pi, 1.2f, -0.1f), 0.0f), 1.0f);
        }
        __syncthreads();
        const int i2 = 2 * tid;
        const float z0 = zs[i2], z1 = zs[i2 + 1];
#pragma unroll 1
        for (int r = 0; r < 8; ++r) {
            const int row = blockIdx.x * 8 + r;
            float2 xv = *(const float2*)(x + row * I_ + i2);
            float a0 = fmaf(-xv.x, z0, 1.0f);
            float a1 = fmaf(-xv.y, z1, 1.0f);
            __nv_bfloat16 h0 = __float2bfloat16_rn(a0);
            __nv_bfloat16 h1 = __float2bfloat16_rn(a1);
            float l0 = a0 - __bfloat162float(h0);
            float l1 = a1 - __bfloat162float(h1);
            float s0 = a0 * a0, s1 = a1 * a1;
            __nv_bfloat162 hh; hh.x = h0; hh.y = h1;
            u32 ah2 = *(u32*)&hh;
            __nv_bfloat16* base = Abig + (size_t)row * KBIG + i2;
            *(u32*)(base + 0 * I_) = ah2;
            *(u32*)(base + 1 * I_) = ah2;
            *(u32*)(base + 2 * I_) = pack2(l0, l1);
            *(u32*)(base + 3 * I_) = pack2(s0, s1);
            *(u32*)(base + 4 * I_) = pack2(s0 * a0, s1 * a1);
            *(u32*)(base + 5 * I_) = pack2(s0 * s0, s1 * s1);
            *(u32*)(base + 6 * I_) = pack2(s0 * s0 * a0, s1 * s1 * a1);
        }
    } else {
        __shared__ float wbuf[64][65];
        const int bt = blockIdx.x - 256;
        const int k0 = (bt >> 2) * 64;
        const int n0 = (bt & 3) * 64;
#pragma unroll
        for (int j = 0; j < 16; ++j) {
            int idx = tid + 256 * j;
            int kr = idx >> 6, nc = idx & 63;
            wbuf[kr][nc] = w[(k0 + kr) * O_ + n0 + nc];
        }
        __syncthreads();
        const int nf = tid >> 2;
        const int ks = (tid & 3) * 16;
#pragma unroll
        for (int j = 0; j < 8; ++j) {
            int kk = ks + 2 * j;
            float w0 = wbuf[kk][nf], w1 = wbuf[kk + 1][nf];
            __nv_bfloat16 h0 = __float2bfloat16_rn(w0);
            __nv_bfloat16 h1 = __float2bfloat16_rn(w1);
            float l0 = w0 - __bfloat162float(h0);
            float l1 = w1 - __bfloat162float(h1);
            float s0 = w0 * w0, s1 = w1 * w1;
            __nv_bfloat162 hh; hh.x = h0; hh.y = h1;
            u32 wh2 = *(u32*)&hh;
            size_t base = (size_t)(n0 + nf) * I_ + k0 + kk;
            size_t segstr = (size_t)O_ * I_;
            *(u32*)(Bbig + base + 0 * segstr) = wh2;
            *(u32*)(Bbig + base + 1 * segstr) = pack2(l0, l1);
            *(u32*)(Bbig + base + 2 * segstr) = wh2;
            *(u32*)(Bbig + base + 3 * segstr) = pack2(s0 * 0.5f, s1 * 0.5f);
            *(u32*)(Bbig + base + 4 * segstr) = pack2(s0 * w0 * (1.f/3.f), s1 * w1 * (1.f/3.f));
            *(u32*)(Bbig + base + 5 * segstr) = pack2(s0 * s0 * 0.25f, s1 * s1 * 0.25f);
            *(u32*)(Bbig + base + 6 * segstr) = pack2(s0 * s0 * w0 * 0.2f, s1 * s1 * w1 * 0.2f);
        }
    }
}

// ---------------- K2: GEMM, warp-split-K, chunk pairs, x4 B-ldmatrix ----------------
__global__ __launch_bounds__(256) void l0_gemm(float* __restrict__ out)
{
    extern __shared__ __align__(1024) char smem[];
    const u32 sb = (u32)__cvta_generic_to_shared(smem);

    const int tid = threadIdx.x;
    const int lane = tid & 31;
    const int wid = tid >> 5;
    const int wn = wid >> 2;          // N-half (0,1)
    const int wk = wid & 3;           // K-quarter (k16 slice within chunk)
    const int m0 = (blockIdx.x >> 2) * CM;
    const int n0 = (blockIdx.x & 3) * CN;

    // ---- Strength-reduced copy bases (per-thread constants) ----
    const int rA = tid >> 3, c8 = tid & 7;
    const u32 aOff = (u32)(rA * 128 + ((c8 * 16) ^ ((rA & 7) * 16)));
    const __nv_bfloat16* aBase = Abig + (size_t)(m0 + rA) * KBIG + c8 * 8;
    const int rB0 = rA, rB1 = rA + 32;
    const u32 bOff0 = aOff;   // same formula, same r
    const u32 bOff1 = (u32)(rB1 * 128 + ((c8 * 16) ^ ((rB1 & 7) * 16)));
    const __nv_bfloat16* bBase0 = Bbig + (size_t)(n0 + rB0) * I_ + c8 * 8;
    const __nv_bfloat16* bBase1 = Bbig + (size_t)(n0 + rB1) * I_ + c8 * 8;

#define PREFP(p, buf)                                                           \
    {                                                                           \
        if ((p) < NPAIR) {                                                      \
            _Pragma("unroll") for (int cc = 0; cc < 2; ++cc) {                  \
                const int c = 2 * (p) + cc;                                     \
                const int boffe = (c >> 3) * (O_ * I_) + (c & 7) * CK;          \
                const u32 sc = sb + (u32)((buf) * PBUF + cc * CBUF);            \
                cpa16(sc + aOff, aBase + c * CK);                               \
                cpa16(sc + 4096 + bOff0, bBase0 + boffe);                       \
                cpa16(sc + 4096 + bOff1, bBase1 + boffe);                       \
            }                                                                   \
        }                                                                       \
        asm volatile("cp.async.commit_group;");                                 \
    }

    PREFP(0, 0);
    PREFP(1, 1);

    float acc[2][4][4];
#pragma unroll
    for (int mt = 0; mt < 2; ++mt)
#pragma unroll
        for (int nt = 0; nt < 4; ++nt)
#pragma unroll
            for (int e = 0; e < 4; ++e) acc[mt][nt][e] = 0.0f;

    // ---- Precomputed ldmatrix byte offsets (loop-invariant) ----
    // A (x4, validated): lanes 0-15 rows, lanes 16-31 +16B k.
    u32 byteA[2];
    {
        const int rowAin = lane & 15;
        const u32 colA = (u32)(wk * 32 + (lane >> 4) * 16);
#pragma unroll
        for (int mt = 0; mt < 2; ++mt) {
            u32 row = (u32)(mt * 16 + rowAin);
            byteA[mt] = row * 128 + (colA ^ ((row & 7) * 16));
        }
    }
    // B (x4, custom lane groups): grp = lane>>3: (n8-tile, k-half) =
    // ((grp>>1), (grp&1)) -> regs {b0,b1 of nt0, b0,b1 of nt1}.
    u32 byteB[2];
    {
        const int grp = lane >> 3, rb = lane & 7;
        const u32 kcol = (u32)(wk * 32 + (grp & 1) * 16);
#pragma unroll
        for (int ntp = 0; ntp < 2; ++ntp) {
            u32 row = (u32)(wn * 32 + ntp * 16 + ((grp >> 1) & 1) * 8 + rb);
            byteB[ntp] = row * 128 + (kcol ^ ((row & 7) * 16));
        }
    }

#define CHUNKC(sC)                                                              \
    {                                                                           \
        u32 aF[2][4], bQ[2][4];                                                 \
        _Pragma("unroll") for (int mt = 0; mt < 2; ++mt)                        \
            asm volatile("ldmatrix.sync.aligned.m8n8.x4.shared.b16 "            \
                         "{%0,%1,%2,%3}, [%4];"                                 \
                         : "=r"(aF[mt][0]), "=r"(aF[mt][1]),                    \
                           "=r"(aF[mt][2]), "=r"(aF[mt][3])                     \
                         : "r"((sC) + byteA[mt]));                              \
        _Pragma("unroll") for (int ntp = 0; ntp < 2; ++ntp)                     \
            asm volatile("ldmatrix.sync.aligned.m8n8.x4.shared.b16 "            \
                         "{%0,%1,%2,%3}, [%4];"                                 \
                         : "=r"(bQ[ntp][0]), "=r"(bQ[ntp][1]),                  \
                           "=r"(bQ[ntp][2]), "=r"(bQ[ntp][3])                   \
                         : "r"((sC) + 4096 + byteB[ntp]));                      \
        _Pragma("unroll") for (int mt = 0; mt < 2; ++mt)                        \
            _Pragma("unroll") for (int nt = 0; nt < 4; ++nt)                    \
                asm volatile(                                                   \
                    "mma.sync.aligned.m16n8k16.row.col.f32.bf16.bf16.f32 "      \
                    "{%0,%1,%2,%3}, {%4,%5,%6,%7}, {%8,%9}, {%0,%1,%2,%3};"     \
                    : "+f"(acc[mt][nt][0]), "+f"(acc[mt][nt][1]),               \
                      "+f"(acc[mt][nt][2]), "+f"(acc[mt][nt][3])                \
                    : "r"(aF[mt][0]), "r"(aF[mt][1]),                           \
                      "r"(aF[mt][2]), "r"(aF[mt][3]),                           \
                      "r"(bQ[nt >> 1][(nt & 1) * 2]),                           \
                      "r"(bQ[nt >> 1][(nt & 1) * 2 + 1]));                      \
    }

#pragma unroll 1
    for (int p = 0; p < NPAIR; ++p) {
        // Proven protocol at pair granularity: wait_group 1 -> this thread's
        // commits through pair p landed; __syncthreads -> all threads' copies
        // of pair p visible AND all threads finished pair p-1, so buffer
        // (p+2)%3 (last held pair p-1) is free to overwrite.
        asm volatile("cp.async.wait_group 1;");
        __syncthreads();
        PREFP(p + 2, (p + 2) % 3);

        const u32 base = sb + (u32)((p % 3) * PBUF);
        CHUNKC(base);
        CHUNKC(base + CBUF);
    }

    // Drain all pending cp.async before repurposing the ring smem as psum.
    asm volatile("cp.async.wait_group 0;");
    __syncthreads();

    // psum[wid][32][32] f32 (32KB). Frag (c0,c1)->(row l>>2, col 2(l&3));
    // (c2,c3)->row+8.
    float* psum = (float*)smem;
    {
        float* pw = psum + wid * (32 * 32);
        const int r0 = lane >> 2;
        const int c0 = (lane & 3) * 2;
#pragma unroll
        for (int mt = 0; mt < 2; ++mt)
#pragma unroll
            for (int nt = 0; nt < 4; ++nt) {
                float* t = pw + (mt * 16 + r0) * 32 + nt * 8 + c0;
                *(float2*)(t)          = make_float2(acc[mt][nt][0], acc[mt][nt][1]);
                *(float2*)(t + 8 * 32) = make_float2(acc[mt][nt][2], acc[mt][nt][3]);
            }
    }
    __syncthreads();

    // Reduce over 4 K-quarters in fixed order; out = exp(-S).
#pragma unroll
    for (int j = 0; j < 8; ++j) {
        int idx = tid + 256 * j;          // 0..2047 over 32x64 tile
        int m = idx >> 6;
        int n = idx & 63;
        const float* pq = psum + ((n >> 5) * 4) * (32 * 32) + m * 32 + (n & 31);
        float s = pq[0] + pq[1024] + pq[2048] + pq[3072];
        out[(m0 + m) * O_ + n0 + n] = expf(-s);
    }
}

extern "C" void kernel_launch(void* const* d_in, const int* in_sizes, int n_in,
                              void* d_out, int out_size) {
    const float* x = nullptr;
    const float* w = nullptr;
    const float* qz = nullptr;
    for (int i = 0; i < n_in; ++i) {
        if (in_sizes[i] == B_ * I_)      x  = (const float*)d_in[i];
        else if (in_sizes[i] == I_ * O_) w  = (const float*)d_in[i];
        else if (in_sizes[i] == I_)      qz = (const float*)d_in[i];
    }
    cudaFuncSetAttribute(l0_gemm, cudaFuncAttributeMaxDynamicSharedMemorySize, GEMM_SMEM);
    l0_prep<<<288, 256>>>(x, w, qz);
    l0_gemm<<<(B_ / CM) * (O_ / CN), 256, GEMM_SMEM>>>((float*)d_out);
}